// round 14
// baseline (speedup 1.0000x reference)
#include <cuda_runtime.h>
#include <math.h>

#define C 128
#define H 256
#define W 256
#define HW (H * W)
#define YA 16
#define XA 16
#define NPART 8  // stats partials per channel

// Deterministic two-stage reduction scratch (no allocations allowed).
__device__ float2 g_ps[C * NPART];

// PyTorch bicubic convolution kernel, a = -0.75
__device__ __forceinline__ float cubic_w(float t) {
    const float a = -0.75f;
    float at = fabsf(t);
    float nr = ((a + 2.f) * at - (a + 3.f)) * at * at + 1.f;
    float fr = (((at - 5.f) * at + 8.f) * at - 4.f) * a;
    return at <= 1.f ? nr : (at < 2.f ? fr : 0.f);
}

// Row of the (3*S, 4) bicubic weight matrix with index clamping folded in.
__device__ __forceinline__ void bicubic_w4(int o_full, float inv_out_times_in, float w[4]) {
    float src = ((float)o_full + 0.5f) * inv_out_times_in - 0.5f;
    float fi0 = floorf(src);
    float t = src - fi0;
    int b = (int)fi0;
    w[0] = w[1] = w[2] = w[3] = 0.f;
#pragma unroll
    for (int k = -1; k <= 2; k++) {
        int idx = b + k;
        idx = idx < 0 ? 0 : (idx > 3 ? 3 : idx);
        w[idx] += cubic_w(t - (float)k);
    }
}

// Kernel 1: 1024 blocks; block b handles eighth (b&7) of channel (b>>3).
__global__ void __launch_bounds__(256) stats_kernel(const float* __restrict__ x) {
    int c = blockIdx.x >> 3;
    int part = blockIdx.x & 7;
    const float4* px = (const float4*)(x + (unsigned)(C + c) * HW + (unsigned)part * (HW / NPART));
    const int N4 = HW / NPART / 4;  // 2048
    float s = 0.f, s2 = 0.f;
#pragma unroll 8
    for (int i = threadIdx.x; i < N4; i += 256) {
        float4 v = px[i];
        s += (v.x + v.y) + (v.z + v.w);
        s2 += (v.x * v.x + v.y * v.y) + (v.z * v.z + v.w * v.w);
    }
#pragma unroll
    for (int off = 16; off; off >>= 1) {
        s += __shfl_xor_sync(0xffffffffu, s, off);
        s2 += __shfl_xor_sync(0xffffffffu, s2, off);
    }
    __shared__ float ws[8], ws2[8];
    int lane = threadIdx.x & 31, wid = threadIdx.x >> 5;
    if (lane == 0) { ws[wid] = s; ws2[wid] = s2; }
    __syncthreads();
    if (wid == 0 && lane < 8) {
        s = ws[lane];
        s2 = ws2[lane];
#pragma unroll
        for (int off = 4; off; off >>= 1) {
            s += __shfl_xor_sync(0xffu, s, off);
            s2 += __shfl_xor_sync(0xffu, s2, off);
        }
        if (lane == 0) g_ps[blockIdx.x] = make_float2(s, s2);
    }
}

// Finalize per-channel stats from partials (cheap, L2-cached broadcast).
__device__ __forceinline__ void finalize_stats(int c, float& mean, float& std) {
    float s = 0.f, s2 = 0.f;
#pragma unroll
    for (int p = 0; p < NPART; p++) {
        float2 v = g_ps[c * NPART + p];
        s += v.x;
        s2 += v.y;
    }
    float n = (float)HW;
    mean = s / n;
    float var = (s2 - n * mean * mean) / (n - 1.f);  // unbiased
    std = sqrtf(var);
}

// Kernel 2: grid (C, 16). y in [0,8): real half (32-row chunks). y in
// [8,16): pre half (32-row streaming). Reg cap 51 (5 CTA/SM -> 1280 thr,
// 62% occ ceiling) — the simple loop sits at ~60 regs naturally, so this
// is a mild squeeze, unlike the heavy-batched R2 code that spilled at 48.
__global__ void __launch_bounds__(256, 5) norm_kernel(
    const float* __restrict__ x,
    const float* __restrict__ mtab,
    const float* __restrict__ stab,
    const float* __restrict__ weight,
    const float* __restrict__ bias,
    const int* __restrict__ d_ya,
    const int* __restrict__ d_xa,
    const int* __restrict__ d_pya,
    const int* __restrict__ d_pxa,
    float* __restrict__ out)
{
    int c = blockIdx.x;
    int by = blockIdx.y;
    int tx = threadIdx.x;   // 0..63 -> 4 cols each
    int ty = threadIdx.y;   // 0..3  -> row phase
    int col = tx * 4;

    if (by >= 8) {
        // ---------- PRE half: pure streaming normalize (32 rows) ----------
        float mean, std;
        finalize_stats(c, mean, std);
        float k = weight[c] / std;
        float b = bias[c];

        const float* xp = x + (unsigned)(C + c) * HW;
        float* outp = out + (unsigned)(C + c) * HW;
        int r0 = (by - 8) * 32;

#pragma unroll
        for (int it = 0; it < 8; it++) {
            unsigned o = (unsigned)(r0 + ty + it * 4) * W + col;
            float4 v = *(const float4*)(xp + o);
            float4 ov;
            ov.x = (v.x - mean) * k + b;
            ov.y = (v.y - mean) * k + b;
            ov.z = (v.z - mean) * k + b;
            ov.w = (v.w - mean) * k + b;
            *(float4*)(outp + o) = ov;
        }
        return;
    }

    // ---------- REAL half: bicubic maps + normalize (32 rows) ----------
    __shared__ float rowm[4][W];   // mean patch rows projected onto output cols
    __shared__ float rowsi[4][W];  // (weight/std) patch rows projected
    __shared__ float wyt[32][4];   // per-row y-weights for this block's chunk
    __shared__ float pm[16], psi[16];
    __shared__ float s_pmean, s_pstd, s_wgt, s_bias;

    int tid = ty * 64 + tx;
    int r0 = by * 32;

    if (tid == 0) {
        float mean, std;
        finalize_stats(c, mean, std);
        s_pmean = mean;
        s_pstd = std;
        s_wgt = weight[c];
        s_bias = bias[c];
    }
    __syncthreads();

    // 4x4 anchor patch (with pre-stat substitution)
    if (tid < 16) {
        int j = tid >> 2, i = tid & 3;
        int yst = min(max(*d_ya, 0), YA - 1);  // dynamic_slice start clamp
        int xst = min(max(*d_xa, 0), XA - 1);
        int ry = min(max(yst + j - 1, 0), YA - 1);  // edge padding
        int rx = min(max(xst + i - 1, 0), XA - 1);
        float mv, sv;
        if (ry == *d_pya && rx == *d_pxa) {
            mv = s_pmean;
            sv = s_pstd;
        } else {
            mv = mtab[(ry * XA + rx) * C + c];
            sv = stab[(ry * XA + rx) * C + c];
        }
        pm[tid] = mv;
        psi[tid] = s_wgt / sv;  // weight folded in
    }
    // per-row y-weights for this chunk's 32 rows
    if (tid >= 32 && tid < 64) {
        int lr = tid - 32;
        float wy[4];
        bicubic_w4(r0 + lr + H / 2, 4.0f / (3.0f * (float)H), wy);
        wyt[lr][0] = wy[0]; wyt[lr][1] = wy[1]; wyt[lr][2] = wy[2]; wyt[lr][3] = wy[3];
    }
    __syncthreads();

    // project patch through Wx for every output column
    {
        float wx[4];
        bicubic_w4(tid + W / 2, 4.0f / (3.0f * (float)W), wx);
#pragma unroll
        for (int y = 0; y < 4; y++) {
            rowm[y][tid] = pm[y * 4 + 0] * wx[0] + pm[y * 4 + 1] * wx[1] +
                           pm[y * 4 + 2] * wx[2] + pm[y * 4 + 3] * wx[3];
            rowsi[y][tid] = psi[y * 4 + 0] * wx[0] + psi[y * 4 + 1] * wx[1] +
                            psi[y * 4 + 2] * wx[2] + psi[y * 4 + 3] * wx[3];
        }
    }
    __syncthreads();

    float bs = s_bias;
    const float* xr = x + (unsigned)c * HW;
    float* outr = out + (unsigned)c * HW;

#pragma unroll
    for (int it = 0; it < 8; it++) {
        int lr = ty + it * 4;
        float w0 = wyt[lr][0], w1 = wyt[lr][1], w2 = wyt[lr][2], w3 = wyt[lr][3];

        float m[4], si[4];
#pragma unroll
        for (int j = 0; j < 4; j++) {
            m[j] = w0 * rowm[0][col + j] + w1 * rowm[1][col + j] +
                   w2 * rowm[2][col + j] + w3 * rowm[3][col + j];
            si[j] = w0 * rowsi[0][col + j] + w1 * rowsi[1][col + j] +
                    w2 * rowsi[2][col + j] + w3 * rowsi[3][col + j];
        }

        unsigned o = (unsigned)(r0 + lr) * W + col;
        float4 vr = *(const float4*)(xr + o);
        float4 orv;
        orv.x = (vr.x - m[0]) * si[0] + bs;
        orv.y = (vr.y - m[1]) * si[1] + bs;
        orv.z = (vr.z - m[2]) * si[2] + bs;
        orv.w = (vr.w - m[3]) * si[3] + bs;
        *(float4*)(outr + o) = orv;
    }
}

extern "C" void kernel_launch(void* const* d_in, const int* in_sizes, int n_in,
                              void* d_out, int out_size) {
    const float* x = (const float*)d_in[0];        // (2, C, H, W)
    const float* mtab = (const float*)d_in[1];     // (YA, XA, C)
    const float* stab = (const float*)d_in[2];     // (YA, XA, C)
    const float* weight = (const float*)d_in[3];   // (1, C, 1, 1)
    const float* bias = (const float*)d_in[4];     // (1, C, 1, 1)
    const int* ya = (const int*)d_in[5];
    const int* xa = (const int*)d_in[6];
    const int* pya = (const int*)d_in[7];
    const int* pxa = (const int*)d_in[8];
    float* out = (float*)d_out;

    stats_kernel<<<C * NPART, 256>>>(x);
    norm_kernel<<<dim3(C, 16), dim3(64, 4)>>>(x, mtab, stab, weight, bias,
                                              ya, xa, pya, pxa, out);
}

// round 15
// speedup vs baseline: 1.3815x; 1.3815x over previous
#include <cuda_runtime.h>
#include <math.h>

#define C 128
#define H 256
#define W 256
#define HW (H * W)
#define YA 16
#define XA 16
#define NPART 8  // stats partials per channel

// Deterministic two-stage reduction scratch (no allocations allowed).
__device__ float2 g_ps[C * NPART];

// PyTorch bicubic convolution kernel, a = -0.75
__device__ __forceinline__ float cubic_w(float t) {
    const float a = -0.75f;
    float at = fabsf(t);
    float nr = ((a + 2.f) * at - (a + 3.f)) * at * at + 1.f;
    float fr = (((at - 5.f) * at + 8.f) * at - 4.f) * a;
    return at <= 1.f ? nr : (at < 2.f ? fr : 0.f);
}

// Row of the (3*S, 4) bicubic weight matrix with index clamping folded in.
__device__ __forceinline__ void bicubic_w4(int o_full, float inv_out_times_in, float w[4]) {
    float src = ((float)o_full + 0.5f) * inv_out_times_in - 0.5f;
    float fi0 = floorf(src);
    float t = src - fi0;
    int b = (int)fi0;
    w[0] = w[1] = w[2] = w[3] = 0.f;
#pragma unroll
    for (int k = -1; k <= 2; k++) {
        int idx = b + k;
        idx = idx < 0 ? 0 : (idx > 3 ? 3 : idx);
        w[idx] += cubic_w(t - (float)k);
    }
}

// Kernel 1: 1024 blocks; block b handles eighth (b&7) of channel (b>>3).
__global__ void __launch_bounds__(256) stats_kernel(const float* __restrict__ x) {
    int c = blockIdx.x >> 3;
    int part = blockIdx.x & 7;
    const float4* px = (const float4*)(x + (unsigned)(C + c) * HW + (unsigned)part * (HW / NPART));
    const int N4 = HW / NPART / 4;  // 2048
    float s = 0.f, s2 = 0.f;
#pragma unroll 8
    for (int i = threadIdx.x; i < N4; i += 256) {
        float4 v = px[i];
        s += (v.x + v.y) + (v.z + v.w);
        s2 += (v.x * v.x + v.y * v.y) + (v.z * v.z + v.w * v.w);
    }
#pragma unroll
    for (int off = 16; off; off >>= 1) {
        s += __shfl_xor_sync(0xffffffffu, s, off);
        s2 += __shfl_xor_sync(0xffffffffu, s2, off);
    }
    __shared__ float ws[8], ws2[8];
    int lane = threadIdx.x & 31, wid = threadIdx.x >> 5;
    if (lane == 0) { ws[wid] = s; ws2[wid] = s2; }
    __syncthreads();
    if (wid == 0 && lane < 8) {
        s = ws[lane];
        s2 = ws2[lane];
#pragma unroll
        for (int off = 4; off; off >>= 1) {
            s += __shfl_xor_sync(0xffu, s, off);
            s2 += __shfl_xor_sync(0xffu, s2, off);
        }
        if (lane == 0) g_ps[blockIdx.x] = make_float2(s, s2);
    }
}

// Finalize per-channel stats from partials (cheap, L2-cached broadcast).
__device__ __forceinline__ void finalize_stats(int c, float& mean, float& std) {
    float s = 0.f, s2 = 0.f;
#pragma unroll
    for (int p = 0; p < NPART; p++) {
        float2 v = g_ps[c * NPART + p];
        s += v.x;
        s2 += v.y;
    }
    float n = (float)HW;
    mean = s / n;
    float var = (s2 - n * mean * mean) / (n - 1.f);  // unbiased
    std = sqrtf(var);
}

// Kernel 2: grid (C, 16). y in [0,8): real half (32-row chunks, maps built
// per block). y in [8,16): pre half (pure streaming). 64-reg cap = exactly
// the RF capacity at 4 CTA/SM x 256 thr; verified optimum (R10: 31.1us).
__global__ void __launch_bounds__(256, 4) norm_kernel(
    const float* __restrict__ x,
    const float* __restrict__ mtab,
    const float* __restrict__ stab,
    const float* __restrict__ weight,
    const float* __restrict__ bias,
    const int* __restrict__ d_ya,
    const int* __restrict__ d_xa,
    const int* __restrict__ d_pya,
    const int* __restrict__ d_pxa,
    float* __restrict__ out)
{
    int c = blockIdx.x;
    int by = blockIdx.y;
    int tx = threadIdx.x;   // 0..63 -> 4 cols each
    int ty = threadIdx.y;   // 0..3  -> row phase
    int col = tx * 4;

    if (by >= 8) {
        // ---------- PRE half: pure streaming normalize (32 rows) ----------
        float mean, std;
        finalize_stats(c, mean, std);
        float k = weight[c] / std;
        float b = bias[c];

        const float* xp = x + (unsigned)(C + c) * HW;
        float* outp = out + (unsigned)(C + c) * HW;
        int r0 = (by - 8) * 32;

#pragma unroll
        for (int it = 0; it < 8; it++) {
            unsigned o = (unsigned)(r0 + ty + it * 4) * W + col;
            float4 v = *(const float4*)(xp + o);
            float4 ov;
            ov.x = (v.x - mean) * k + b;
            ov.y = (v.y - mean) * k + b;
            ov.z = (v.z - mean) * k + b;
            ov.w = (v.w - mean) * k + b;
            *(float4*)(outp + o) = ov;
        }
        return;
    }

    // ---------- REAL half: bicubic maps + normalize (32 rows) ----------
    __shared__ float rowm[4][W];   // mean patch rows projected onto output cols
    __shared__ float rowsi[4][W];  // (weight/std) patch rows projected
    __shared__ float wyt[32][4];   // per-row y-weights for this block's chunk
    __shared__ float pm[16], psi[16];
    __shared__ float s_pmean, s_pstd, s_wgt, s_bias;

    int tid = ty * 64 + tx;
    int r0 = by * 32;

    if (tid == 0) {
        float mean, std;
        finalize_stats(c, mean, std);
        s_pmean = mean;
        s_pstd = std;
        s_wgt = weight[c];
        s_bias = bias[c];
    }
    __syncthreads();

    // 4x4 anchor patch (with pre-stat substitution)
    if (tid < 16) {
        int j = tid >> 2, i = tid & 3;
        int yst = min(max(*d_ya, 0), YA - 1);  // dynamic_slice start clamp
        int xst = min(max(*d_xa, 0), XA - 1);
        int ry = min(max(yst + j - 1, 0), YA - 1);  // edge padding
        int rx = min(max(xst + i - 1, 0), XA - 1);
        float mv, sv;
        if (ry == *d_pya && rx == *d_pxa) {
            mv = s_pmean;
            sv = s_pstd;
        } else {
            mv = mtab[(ry * XA + rx) * C + c];
            sv = stab[(ry * XA + rx) * C + c];
        }
        pm[tid] = mv;
        psi[tid] = s_wgt / sv;  // weight folded in
    }
    // per-row y-weights for this chunk's 32 rows
    if (tid >= 32 && tid < 64) {
        int lr = tid - 32;
        float wy[4];
        bicubic_w4(r0 + lr + H / 2, 4.0f / (3.0f * (float)H), wy);
        wyt[lr][0] = wy[0]; wyt[lr][1] = wy[1]; wyt[lr][2] = wy[2]; wyt[lr][3] = wy[3];
    }
    __syncthreads();

    // project patch through Wx for every output column
    {
        float wx[4];
        bicubic_w4(tid + W / 2, 4.0f / (3.0f * (float)W), wx);
#pragma unroll
        for (int y = 0; y < 4; y++) {
            rowm[y][tid] = pm[y * 4 + 0] * wx[0] + pm[y * 4 + 1] * wx[1] +
                           pm[y * 4 + 2] * wx[2] + pm[y * 4 + 3] * wx[3];
            rowsi[y][tid] = psi[y * 4 + 0] * wx[0] + psi[y * 4 + 1] * wx[1] +
                            psi[y * 4 + 2] * wx[2] + psi[y * 4 + 3] * wx[3];
        }
    }
    __syncthreads();

    float bs = s_bias;
    const float* xr = x + (unsigned)c * HW;
    float* outr = out + (unsigned)c * HW;

#pragma unroll
    for (int it = 0; it < 8; it++) {
        int lr = ty + it * 4;
        float w0 = wyt[lr][0], w1 = wyt[lr][1], w2 = wyt[lr][2], w3 = wyt[lr][3];

        float m[4], si[4];
#pragma unroll
        for (int j = 0; j < 4; j++) {
            m[j] = w0 * rowm[0][col + j] + w1 * rowm[1][col + j] +
                   w2 * rowm[2][col + j] + w3 * rowm[3][col + j];
            si[j] = w0 * rowsi[0][col + j] + w1 * rowsi[1][col + j] +
                    w2 * rowsi[2][col + j] + w3 * rowsi[3][col + j];
        }

        unsigned o = (unsigned)(r0 + lr) * W + col;
        float4 vr = *(const float4*)(xr + o);
        float4 orv;
        orv.x = (vr.x - m[0]) * si[0] + bs;
        orv.y = (vr.y - m[1]) * si[1] + bs;
        orv.z = (vr.z - m[2]) * si[2] + bs;
        orv.w = (vr.w - m[3]) * si[3] + bs;
        *(float4*)(outr + o) = orv;
    }
}

extern "C" void kernel_launch(void* const* d_in, const int* in_sizes, int n_in,
                              void* d_out, int out_size) {
    const float* x = (const float*)d_in[0];        // (2, C, H, W)
    const float* mtab = (const float*)d_in[1];     // (YA, XA, C)
    const float* stab = (const float*)d_in[2];     // (YA, XA, C)
    const float* weight = (const float*)d_in[3];   // (1, C, 1, 1)
    const float* bias = (const float*)d_in[4];     // (1, C, 1, 1)
    const int* ya = (const int*)d_in[5];
    const int* xa = (const int*)d_in[6];
    const int* pya = (const int*)d_in[7];
    const int* pxa = (const int*)d_in[8];
    float* out = (float*)d_out;

    stats_kernel<<<C * NPART, 256>>>(x);
    norm_kernel<<<dim3(C, 16), dim3(64, 4)>>>(x, mtab, stab, weight, bias,
                                              ya, xa, pya, pxa, out);
}

// round 16
// speedup vs baseline: 1.4641x; 1.0598x over previous
#include <cuda_runtime.h>
#include <math.h>

#define C 128
#define H 256
#define W 256
#define HW (H * W)
#define YA 16
#define XA 16
#define NPART 8  // stats partials per channel

// Deterministic two-stage reduction scratch (no allocations allowed).
__device__ float2 g_ps[C * NPART];

// PyTorch bicubic convolution kernel, a = -0.75
__device__ __forceinline__ float cubic_w(float t) {
    const float a = -0.75f;
    float at = fabsf(t);
    float nr = ((a + 2.f) * at - (a + 3.f)) * at * at + 1.f;
    float fr = (((at - 5.f) * at + 8.f) * at - 4.f) * a;
    return at <= 1.f ? nr : (at < 2.f ? fr : 0.f);
}

// Row of the (3*S, 4) bicubic weight matrix with index clamping folded in.
__device__ __forceinline__ void bicubic_w4(int o_full, float inv_out_times_in, float w[4]) {
    float src = ((float)o_full + 0.5f) * inv_out_times_in - 0.5f;
    float fi0 = floorf(src);
    float t = src - fi0;
    int b = (int)fi0;
    w[0] = w[1] = w[2] = w[3] = 0.f;
#pragma unroll
    for (int k = -1; k <= 2; k++) {
        int idx = b + k;
        idx = idx < 0 ? 0 : (idx > 3 ? 3 : idx);
        w[idx] += cubic_w(t - (float)k);
    }
}

// Kernel 1: 1024 blocks; block b handles eighth (b&7) of channel (b>>3).
__global__ void __launch_bounds__(256) stats_kernel(const float* __restrict__ x) {
    int c = blockIdx.x >> 3;
    int part = blockIdx.x & 7;
    const float4* px = (const float4*)(x + (unsigned)(C + c) * HW + (unsigned)part * (HW / NPART));
    const int N4 = HW / NPART / 4;  // 2048
    float s = 0.f, s2 = 0.f;
#pragma unroll 8
    for (int i = threadIdx.x; i < N4; i += 256) {
        float4 v = px[i];
        s += (v.x + v.y) + (v.z + v.w);
        s2 += (v.x * v.x + v.y * v.y) + (v.z * v.z + v.w * v.w);
    }
#pragma unroll
    for (int off = 16; off; off >>= 1) {
        s += __shfl_xor_sync(0xffffffffu, s, off);
        s2 += __shfl_xor_sync(0xffffffffu, s2, off);
    }
    __shared__ float ws[8], ws2[8];
    int lane = threadIdx.x & 31, wid = threadIdx.x >> 5;
    if (lane == 0) { ws[wid] = s; ws2[wid] = s2; }
    __syncthreads();
    if (wid == 0 && lane < 8) {
        s = ws[lane];
        s2 = ws2[lane];
#pragma unroll
        for (int off = 4; off; off >>= 1) {
            s += __shfl_xor_sync(0xffu, s, off);
            s2 += __shfl_xor_sync(0xffu, s2, off);
        }
        if (lane == 0) g_ps[blockIdx.x] = make_float2(s, s2);
    }
}

// Finalize per-channel stats from partials (cheap, L2-cached broadcast).
__device__ __forceinline__ void finalize_stats(int c, float& mean, float& std) {
    float s = 0.f, s2 = 0.f;
#pragma unroll
    for (int p = 0; p < NPART; p++) {
        float2 v = g_ps[c * NPART + p];
        s += v.x;
        s2 += v.y;
    }
    float n = (float)HW;
    mean = s / n;
    float var = (s2 - n * mean * mean) / (n - 1.f);  // unbiased
    std = sqrtf(var);
}

// Kernel 2: grid (C, 16). y in [0,8): real half; y in [8,16): pre half.
// Loads: default policy (pre half hits L2, warmed by stats). Stores: __stcs
// (write-once output, evict-first) so out lines don't evict x's residency.
__global__ void __launch_bounds__(256, 4) norm_kernel(
    const float* __restrict__ x,
    const float* __restrict__ mtab,
    const float* __restrict__ stab,
    const float* __restrict__ weight,
    const float* __restrict__ bias,
    const int* __restrict__ d_ya,
    const int* __restrict__ d_xa,
    const int* __restrict__ d_pya,
    const int* __restrict__ d_pxa,
    float* __restrict__ out)
{
    int c = blockIdx.x;
    int by = blockIdx.y;
    int tx = threadIdx.x;   // 0..63 -> 4 cols each
    int ty = threadIdx.y;   // 0..3  -> row phase
    int col = tx * 4;

    if (by >= 8) {
        // ---------- PRE half: pure streaming normalize (32 rows) ----------
        float mean, std;
        finalize_stats(c, mean, std);
        float k = weight[c] / std;
        float b = bias[c];

        const float* xp = x + (unsigned)(C + c) * HW;
        float* outp = out + (unsigned)(C + c) * HW;
        int r0 = (by - 8) * 32;

#pragma unroll
        for (int it = 0; it < 8; it++) {
            unsigned o = (unsigned)(r0 + ty + it * 4) * W + col;
            float4 v = *(const float4*)(xp + o);
            float4 ov;
            ov.x = (v.x - mean) * k + b;
            ov.y = (v.y - mean) * k + b;
            ov.z = (v.z - mean) * k + b;
            ov.w = (v.w - mean) * k + b;
            __stcs((float4*)(outp + o), ov);
        }
        return;
    }

    // ---------- REAL half: bicubic maps + normalize (32 rows) ----------
    __shared__ float rowm[4][W];   // mean patch rows projected onto output cols
    __shared__ float rowsi[4][W];  // (weight/std) patch rows projected
    __shared__ float wyt[32][4];   // per-row y-weights for this block's chunk
    __shared__ float pm[16], psi[16];
    __shared__ float s_pmean, s_pstd, s_wgt, s_bias;

    int tid = ty * 64 + tx;
    int r0 = by * 32;

    if (tid == 0) {
        float mean, std;
        finalize_stats(c, mean, std);
        s_pmean = mean;
        s_pstd = std;
        s_wgt = weight[c];
        s_bias = bias[c];
    }
    __syncthreads();

    // 4x4 anchor patch (with pre-stat substitution)
    if (tid < 16) {
        int j = tid >> 2, i = tid & 3;
        int yst = min(max(*d_ya, 0), YA - 1);  // dynamic_slice start clamp
        int xst = min(max(*d_xa, 0), XA - 1);
        int ry = min(max(yst + j - 1, 0), YA - 1);  // edge padding
        int rx = min(max(xst + i - 1, 0), XA - 1);
        float mv, sv;
        if (ry == *d_pya && rx == *d_pxa) {
            mv = s_pmean;
            sv = s_pstd;
        } else {
            mv = mtab[(ry * XA + rx) * C + c];
            sv = stab[(ry * XA + rx) * C + c];
        }
        pm[tid] = mv;
        psi[tid] = s_wgt / sv;  // weight folded in
    }
    // per-row y-weights for this chunk's 32 rows
    if (tid >= 32 && tid < 64) {
        int lr = tid - 32;
        float wy[4];
        bicubic_w4(r0 + lr + H / 2, 4.0f / (3.0f * (float)H), wy);
        wyt[lr][0] = wy[0]; wyt[lr][1] = wy[1]; wyt[lr][2] = wy[2]; wyt[lr][3] = wy[3];
    }
    __syncthreads();

    // project patch through Wx for every output column
    {
        float wx[4];
        bicubic_w4(tid + W / 2, 4.0f / (3.0f * (float)W), wx);
#pragma unroll
        for (int y = 0; y < 4; y++) {
            rowm[y][tid] = pm[y * 4 + 0] * wx[0] + pm[y * 4 + 1] * wx[1] +
                           pm[y * 4 + 2] * wx[2] + pm[y * 4 + 3] * wx[3];
            rowsi[y][tid] = psi[y * 4 + 0] * wx[0] + psi[y * 4 + 1] * wx[1] +
                            psi[y * 4 + 2] * wx[2] + psi[y * 4 + 3] * wx[3];
        }
    }
    __syncthreads();

    float bs = s_bias;
    const float* xr = x + (unsigned)c * HW;
    float* outr = out + (unsigned)c * HW;

#pragma unroll
    for (int it = 0; it < 8; it++) {
        int lr = ty + it * 4;
        float w0 = wyt[lr][0], w1 = wyt[lr][1], w2 = wyt[lr][2], w3 = wyt[lr][3];

        float m[4], si[4];
#pragma unroll
        for (int j = 0; j < 4; j++) {
            m[j] = w0 * rowm[0][col + j] + w1 * rowm[1][col + j] +
                   w2 * rowm[2][col + j] + w3 * rowm[3][col + j];
            si[j] = w0 * rowsi[0][col + j] + w1 * rowsi[1][col + j] +
                    w2 * rowsi[2][col + j] + w3 * rowsi[3][col + j];
        }

        unsigned o = (unsigned)(r0 + lr) * W + col;
        float4 vr = *(const float4*)(xr + o);
        float4 orv;
        orv.x = (vr.x - m[0]) * si[0] + bs;
        orv.y = (vr.y - m[1]) * si[1] + bs;
        orv.z = (vr.z - m[2]) * si[2] + bs;
        orv.w = (vr.w - m[3]) * si[3] + bs;
        __stcs((float4*)(outr + o), orv);
    }
}

extern "C" void kernel_launch(void* const* d_in, const int* in_sizes, int n_in,
                              void* d_out, int out_size) {
    const float* x = (const float*)d_in[0];        // (2, C, H, W)
    const float* mtab = (const float*)d_in[1];     // (YA, XA, C)
    const float* stab = (const float*)d_in[2];     // (YA, XA, C)
    const float* weight = (const float*)d_in[3];   // (1, C, 1, 1)
    const float* bias = (const float*)d_in[4];     // (1, C, 1, 1)
    const int* ya = (const int*)d_in[5];
    const int* xa = (const int*)d_in[6];
    const int* pya = (const int*)d_in[7];
    const int* pxa = (const int*)d_in[8];
    float* out = (float*)d_out;

    stats_kernel<<<C * NPART, 256>>>(x);
    norm_kernel<<<dim3(C, 16), dim3(64, 4)>>>(x, mtab, stab, weight, bias,
                                              ya, xa, pya, pxa, out);
}